// round 1
// baseline (speedup 1.0000x reference)
#include <cuda_runtime.h>
#include <math.h>

// Problem dims (fixed by the dataset)
#define NN 4
#define HH 512
#define WW 512
#define CC 64

#define CPB     32                 // channels per block
#define THREADS 256
#define ROWLEN  512                // scan length (W in pass1, H in pass2)
#define NCHUNK  8                  // 256 threads / 32 channels
#define CLEN    (ROWLEN / NCHUNK)  // 64
#define LWARM   48                 // warm-up length: err ~ 0.5^48 ~ 4e-15
#define VEC     (ROWLEN * CPB / 4) // float4s per tile = 4096
#define SMEM_BYTES (ROWLEN * CPB * 4) // 65536

// Intermediate (W-filtered) image, same NHWC layout as x. Static device
// scratch (no allocation allowed in kernel_launch).
__device__ float g_scratch[(size_t)NN * HH * WW * CC];

// Forward+backward first-order IIR (a=b=0.5) over a ROWLEN x CPB tile in
// shared memory, in place. Chunk-parallel with warm-up; boundary chunks use
// the exact reference initialization:
//   forward:  y[0]   = 0.5*x[0] + 0.5*x[0]      (c0 = x[0])
//   backward: y[L-1] = y_f[L-1]                  (c1 = y_f[L-1])
// Interior chunk carries are warmed up over LWARM steps (error 0.5^LWARM).
__device__ __forceinline__ void iir_scan_tile(float* s, int tid) {
    const int c     = tid & (CPB - 1);
    const int chunk = tid >> 5;           // 0..7
    const int w0    = chunk * CLEN;
    const int w1    = w0 + CLEN;

    // ---- forward warm-up (read-only) ----
    float carry;
    if (chunk == 0) {
        carry = s[c];                     // y_f[-1] := x[0]  (exact)
    } else {
        const int ws = w0 - LWARM;        // w0 >= 64 > LWARM, always >= 16
        carry = s[ws * CPB + c];          // steady-state approx
        for (int w = ws; w < w0; ++w)
            carry = fmaf(0.5f, s[w * CPB + c], 0.5f * carry);
    }
    __syncthreads();

    // ---- forward scan, in place (own chunk only) ----
    #pragma unroll 8
    for (int w = w0; w < w1; ++w) {
        float v = fmaf(0.5f, s[w * CPB + c], 0.5f * carry);
        s[w * CPB + c] = v;
        carry = v;
    }
    __syncthreads();

    // ---- backward warm-up (read-only on finalized y_f) ----
    {
        const int wl = w1 - 1 + LWARM;
        const int we = (wl < ROWLEN) ? wl : (ROWLEN - 1);
        // carry approximates yb[w1]; for the last chunk, carry = y_f[L-1]
        // makes the first in-place step produce yb[L-1] = y_f[L-1] exactly.
        carry = s[we * CPB + c];
        for (int w = we - 1; w >= w1; --w)
            carry = fmaf(0.5f, s[w * CPB + c], 0.5f * carry);
    }
    __syncthreads();

    // ---- backward scan, in place (own chunk only) ----
    #pragma unroll 8
    for (int w = w1 - 1; w >= w0; --w) {
        float v = fmaf(0.5f, s[w * CPB + c], 0.5f * carry);
        s[w * CPB + c] = v;
        carry = v;
    }
    __syncthreads();
}

// Pass 1: IIR along W. One block per (n*H row, channel-group of 32).
__global__ void __launch_bounds__(THREADS)
pass1_kernel(const float* __restrict__ x) {
    extern __shared__ float s[];
    float4* s4 = reinterpret_cast<float4*>(s);

    const int    nh   = blockIdx.x;                 // n*HH + h
    const int    cg   = blockIdx.y;                 // channel group
    const size_t base = (size_t)nh * (WW * CC) + (size_t)cg * CPB;

    // Coalesced float4 load: per w, 32 consecutive channels = 128B.
    for (int i = threadIdx.x; i < VEC; i += THREADS) {
        const int w  = i >> 3;
        const int c4 = i & 7;
        s4[w * 8 + c4] = *(const float4*)(x + base + (size_t)w * CC + c4 * 4);
    }
    __syncthreads();

    iir_scan_tile(s, threadIdx.x);

    for (int i = threadIdx.x; i < VEC; i += THREADS) {
        const int w  = i >> 3;
        const int c4 = i & 7;
        *(float4*)(g_scratch + base + (size_t)w * CC + c4 * 4) = s4[w * 8 + c4];
    }
}

// Pass 2: IIR along H on the scratch, then residual mix with x -> out.
__global__ void __launch_bounds__(THREADS)
pass2_kernel(const float* __restrict__ x,
             const float* __restrict__ alpha,
             float*       __restrict__ out) {
    extern __shared__ float s[];
    float4* s4 = reinterpret_cast<float4*>(s);
    __shared__ __align__(16) float sm[CPB];

    const int    nw   = blockIdx.x;                 // n*WW + w
    const int    n    = nw >> 9;                    // / 512
    const int    w    = nw & 511;
    const int    cg   = blockIdx.y;
    const size_t base = (size_t)n * (HH * WW * CC) + (size_t)w * CC + (size_t)cg * CPB;

    if (threadIdx.x < CPB) {
        const float a = alpha[cg * CPB + threadIdx.x];
        sm[threadIdx.x] = 1.0f / (1.0f + expf(-a));   // sigmoid mix
    }

    for (int i = threadIdx.x; i < VEC; i += THREADS) {
        const int h  = i >> 3;
        const int c4 = i & 7;
        s4[h * 8 + c4] =
            *(const float4*)(g_scratch + base + (size_t)h * (WW * CC) + c4 * 4);
    }
    __syncthreads();

    iir_scan_tile(s, threadIdx.x);

    for (int i = threadIdx.x; i < VEC; i += THREADS) {
        const int    h  = i >> 3;
        const int    c4 = i & 7;
        const size_t g  = base + (size_t)h * (WW * CC) + c4 * 4;
        const float4 xv = *(const float4*)(x + g);
        const float4 yv = s4[h * 8 + c4];
        const float4 mv = *(const float4*)(&sm[c4 * 4]);
        float4 o;
        o.x = fmaf(mv.x, yv.x - xv.x, xv.x);
        o.y = fmaf(mv.y, yv.y - xv.y, xv.y);
        o.z = fmaf(mv.z, yv.z - xv.z, xv.z);
        o.w = fmaf(mv.w, yv.w - xv.w, xv.w);
        *(float4*)(out + g) = o;
    }
}

extern "C" void kernel_launch(void* const* d_in, const int* in_sizes, int n_in,
                              void* d_out, int out_size) {
    const float* x     = (const float*)d_in[0];
    const float* alpha = (const float*)d_in[1];
    float*       out   = (float*)d_out;

    // 64KB dynamic smem requires explicit opt-in (>48KB). Idempotent,
    // non-stream API: safe under graph capture.
    cudaFuncSetAttribute(pass1_kernel,
                         cudaFuncAttributeMaxDynamicSharedMemorySize, SMEM_BYTES);
    cudaFuncSetAttribute(pass2_kernel,
                         cudaFuncAttributeMaxDynamicSharedMemorySize, SMEM_BYTES);

    dim3 grid1(NN * HH, CC / CPB);
    pass1_kernel<<<grid1, THREADS, SMEM_BYTES>>>(x);

    dim3 grid2(NN * WW, CC / CPB);
    pass2_kernel<<<grid2, THREADS, SMEM_BYTES>>>(x, alpha, out);
}

// round 2
// speedup vs baseline: 1.7058x; 1.7058x over previous
#include <cuda_runtime.h>
#include <cuda_fp16.h>
#include <math.h>

// Problem dims (fixed by the dataset)
#define NN 4
#define HH 512
#define WW 512
#define CC 64

#define CPB     32                 // channels per block
#define THREADS 512
#define ROWLEN  512                // scan length (W in pass1, H in pass2)
#define NCHUNK  (THREADS / CPB)    // 16
#define CLEN    (ROWLEN / NCHUNK)  // 32
#define LWARM   24                 // warm-up: err ~ 0.5^24 ~ 6e-8
#define VEC     (ROWLEN * CPB / 4) // float4s per fp32 tile = 4096
#define VECH    (ROWLEN * CPB / 8) // uint4s (8 halves) per fp16 tile = 2048
#define SMEM_BYTES (ROWLEN * CPB * 4) // 65536

// Intermediate (W-filtered) image in fp16, same NHWC index space as x.
__device__ __half g_scratch[(size_t)NN * HH * WW * CC];

// Forward+backward first-order IIR (a=b=0.5) over a ROWLEN x CPB fp32 tile in
// shared memory, in place. Chunk-parallel with warm-up. Boundary chunks use
// the exact reference initialization (c0 = x[0] forward; c1 = y_f[L-1] back).
// Step form carry = fma(0.5, carry, 0.5*x) keeps the dependent chain at one
// FMA (4 cyc) per step; the 0.5*x mul is off-chain.
__device__ __forceinline__ void iir_scan_tile(float* s, int tid) {
    const int c     = tid & (CPB - 1);
    const int chunk = tid / CPB;          // 0..NCHUNK-1
    const int w0    = chunk * CLEN;
    const int w1    = w0 + CLEN;

    // ---- forward warm-up (read-only) ----
    float carry;
    if (chunk == 0) {
        carry = s[c];                     // y_f[-1] := x[0]  (exact)
    } else {
        const int ws = w0 - LWARM;        // w0 >= 32 > LWARM? w0>=32, ws>=8
        carry = s[ws * CPB + c];
        #pragma unroll
        for (int k = 0; k < LWARM; ++k)
            carry = fmaf(0.5f, carry, 0.5f * s[(ws + k) * CPB + c]);
    }
    __syncthreads();

    // ---- forward scan, in place (own chunk only) ----
    #pragma unroll
    for (int w = w0; w < w1; ++w) {
        carry = fmaf(0.5f, carry, 0.5f * s[w * CPB + c]);
        s[w * CPB + c] = carry;
    }
    __syncthreads();

    // ---- backward warm-up (read-only on finalized y_f) ----
    if (chunk == NCHUNK - 1) {
        // first in-place step at w=L-1 gives y_b[L-1] = y_f[L-1] exactly
        carry = s[(ROWLEN - 1) * CPB + c];
    } else {
        const int we = w1 - 1 + LWARM;    // <= 503 for chunk <= NCHUNK-2
        carry = s[we * CPB + c];
        #pragma unroll
        for (int k = 1; k < LWARM; ++k)
            carry = fmaf(0.5f, carry, 0.5f * s[(we - k) * CPB + c]);
    }
    __syncthreads();

    // ---- backward scan, in place (own chunk only) ----
    #pragma unroll
    for (int w = w1 - 1; w >= w0; --w) {
        carry = fmaf(0.5f, carry, 0.5f * s[w * CPB + c]);
        s[w * CPB + c] = carry;
    }
    __syncthreads();
}

// Pass 1: IIR along W. One block per (n*H row, channel-group of 32).
// Reads x (fp32), writes W-filtered tile to g_scratch (fp16).
__global__ void __launch_bounds__(THREADS)
pass1_kernel(const float* __restrict__ x) {
    extern __shared__ float s[];
    float4* s4 = reinterpret_cast<float4*>(s);

    const int    nh   = blockIdx.x;                 // n*HH + h
    const int    cg   = blockIdx.y;                 // channel group
    const size_t base = (size_t)nh * (WW * CC) + (size_t)cg * CPB;

    #pragma unroll
    for (int i = threadIdx.x; i < VEC; i += THREADS) {
        const int w  = i >> 3;
        const int c4 = i & 7;
        s4[w * 8 + c4] = *(const float4*)(x + base + (size_t)w * CC + c4 * 4);
    }
    __syncthreads();

    iir_scan_tile(s, threadIdx.x);

    // fp16 store: per w, 32 ch = 64B = 4 uint4 (8 halves each)
    #pragma unroll
    for (int i = threadIdx.x; i < VECH; i += THREADS) {
        const int w = i >> 2;
        const int q = i & 3;
        const float* sp = s + w * CPB + q * 8;
        __half2 hv[4];
        #pragma unroll
        for (int k = 0; k < 4; ++k)
            hv[k] = __floats2half2_rn(sp[2 * k], sp[2 * k + 1]);
        *(uint4*)(g_scratch + base + (size_t)w * CC + q * 8) = *(uint4*)hv;
    }
}

// Pass 2: IIR along H on the scratch (fp16 in, fp32 scan), residual mix -> out.
__global__ void __launch_bounds__(THREADS)
pass2_kernel(const float* __restrict__ x,
             const float* __restrict__ alpha,
             float*       __restrict__ out) {
    extern __shared__ float s[];
    float4* s4 = reinterpret_cast<float4*>(s);
    __shared__ __align__(16) float sm[CPB];

    const int    nw   = blockIdx.x;                 // n*WW + w
    const int    n    = nw >> 9;
    const int    w    = nw & 511;
    const int    cg   = blockIdx.y;
    const size_t base = (size_t)n * (HH * WW * CC) + (size_t)w * CC + (size_t)cg * CPB;

    if (threadIdx.x < CPB) {
        const float a = alpha[cg * CPB + threadIdx.x];
        sm[threadIdx.x] = 1.0f / (1.0f + expf(-a));   // sigmoid mix
    }

    // fp16 load from scratch: per h, 4 uint4 of 8 halves
    #pragma unroll
    for (int i = threadIdx.x; i < VECH; i += THREADS) {
        const int h = i >> 2;
        const int q = i & 3;
        uint4 v = *(const uint4*)(g_scratch + base + (size_t)h * (WW * CC) + q * 8);
        const __half2* hv = (const __half2*)&v;
        float* sp = s + h * CPB + q * 8;
        #pragma unroll
        for (int k = 0; k < 4; ++k) {
            float2 f = __half22float2(hv[k]);
            sp[2 * k]     = f.x;
            sp[2 * k + 1] = f.y;
        }
    }
    __syncthreads();

    iir_scan_tile(s, threadIdx.x);

    #pragma unroll
    for (int i = threadIdx.x; i < VEC; i += THREADS) {
        const int    h  = i >> 3;
        const int    c4 = i & 7;
        const size_t g  = base + (size_t)h * (WW * CC) + c4 * 4;
        const float4 xv = *(const float4*)(x + g);
        const float4 yv = s4[h * 8 + c4];
        const float4 mv = *(const float4*)(&sm[c4 * 4]);
        float4 o;
        o.x = fmaf(mv.x, yv.x - xv.x, xv.x);
        o.y = fmaf(mv.y, yv.y - xv.y, xv.y);
        o.z = fmaf(mv.z, yv.z - xv.z, xv.z);
        o.w = fmaf(mv.w, yv.w - xv.w, xv.w);
        *(float4*)(out + g) = o;
    }
}

extern "C" void kernel_launch(void* const* d_in, const int* in_sizes, int n_in,
                              void* d_out, int out_size) {
    const float* x     = (const float*)d_in[0];
    const float* alpha = (const float*)d_in[1];
    float*       out   = (float*)d_out;

    cudaFuncSetAttribute(pass1_kernel,
                         cudaFuncAttributeMaxDynamicSharedMemorySize, SMEM_BYTES);
    cudaFuncSetAttribute(pass2_kernel,
                         cudaFuncAttributeMaxDynamicSharedMemorySize, SMEM_BYTES);

    dim3 grid1(NN * HH, CC / CPB);
    pass1_kernel<<<grid1, THREADS, SMEM_BYTES>>>(x);

    dim3 grid2(NN * WW, CC / CPB);
    pass2_kernel<<<grid2, THREADS, SMEM_BYTES>>>(x, alpha, out);
}